// round 7
// baseline (speedup 1.0000x reference)
#include <cuda_runtime.h>
#include <cuda_fp16.h>

constexpr int B = 1024, F = 784, D = 512;
constexpr int TB = 64, TD = 64, TF = 112;    // 784 = 7 * 112
constexpr int SXH = 120;                      // smem stride in halfs (240B = 15 x 16B chunks, odd)
constexpr int NSTEP = F / TF;                 // 7

// fp16 pre-converted operands (pre-pass kernel fills these).
__device__ __half g_xh[B * F];
__device__ __half g_ch[D * F];   // (Wmin+Wmax)/2
__device__ __half g_rh[D * F];   // (Wmax-Wmin)/2

union U4H {
    uint4 u;
    __half2 h[4];
};

__device__ __forceinline__ unsigned h2u(__half2 v) {
    union { __half2 h; unsigned u; } c; c.h = v; return c.u;
}

__global__ __launch_bounds__(256)
void prep_x(const float* __restrict__ x)
{
    int i = (blockIdx.x * 256 + threadIdx.x) * 8;
    float4 a = *(const float4*)&x[i];
    float4 b = *(const float4*)&x[i + 4];
    uint4 o;
    o.x = h2u(__floats2half2_rn(a.x, a.y));
    o.y = h2u(__floats2half2_rn(a.z, a.w));
    o.z = h2u(__floats2half2_rn(b.x, b.y));
    o.w = h2u(__floats2half2_rn(b.z, b.w));
    *(uint4*)&g_xh[i] = o;
}

__global__ __launch_bounds__(256)
void prep_w(const float* __restrict__ wmin, const float* __restrict__ wmax)
{
    int i = (blockIdx.x * 256 + threadIdx.x) * 8;
    float4 n0 = *(const float4*)&wmin[i];
    float4 n1 = *(const float4*)&wmin[i + 4];
    float4 m0 = *(const float4*)&wmax[i];
    float4 m1 = *(const float4*)&wmax[i + 4];
    uint4 oc, orr;
    oc.x  = h2u(__floats2half2_rn(0.5f*(n0.x+m0.x), 0.5f*(n0.y+m0.y)));
    oc.y  = h2u(__floats2half2_rn(0.5f*(n0.z+m0.z), 0.5f*(n0.w+m0.w)));
    oc.z  = h2u(__floats2half2_rn(0.5f*(n1.x+m1.x), 0.5f*(n1.y+m1.y)));
    oc.w  = h2u(__floats2half2_rn(0.5f*(n1.z+m1.z), 0.5f*(n1.w+m1.w)));
    orr.x = h2u(__floats2half2_rn(0.5f*(m0.x-n0.x), 0.5f*(m0.y-n0.y)));
    orr.y = h2u(__floats2half2_rn(0.5f*(m0.z-n0.z), 0.5f*(m0.w-n0.w)));
    orr.z = h2u(__floats2half2_rn(0.5f*(m1.x-n1.x), 0.5f*(m1.y-n1.y)));
    orr.w = h2u(__floats2half2_rn(0.5f*(m1.z-n1.z), 0.5f*(m1.w-n1.w)));
    *(uint4*)&g_ch[i] = oc;
    *(uint4*)&g_rh[i] = orr;
}

__global__ __launch_bounds__(256)
void dendral_kernel(float* __restrict__ out)
{
    __shared__ __half sx[TB * SXH];
    __shared__ __half sc[TD * SXH];
    __shared__ __half sr[TD * SXH];

    const int tid = threadIdx.x;
    const int tx  = tid & 15;     // d lane
    const int ty  = tid >> 4;     // b lane
    const int d0  = blockIdx.x * TD;
    const int b0  = blockIdx.y * TB;

    const __half2 INF2 = __halves2half2(__ushort_as_half(0x7C00), __ushort_as_half(0x7C00));
    __half2 acc[4][4];
    #pragma unroll
    for (int i = 0; i < 4; ++i)
        #pragma unroll
        for (int j = 0; j < 4; ++j) acc[i][j] = INF2;

    for (int k = 0; k < NSTEP; ++k) {
        const int f0 = k * TF;
        __syncthreads();

        // Stage fp16 tiles: 64 rows x 14 uint4 (8 halfs each) per array = 896 uint4.
        #pragma unroll
        for (int t = 0; t < 4; ++t) {
            int idx = tid + t * 256;
            if (idx < 896) {
                int row = idx / 14;
                int c8  = (idx % 14) * 8;
                int so  = row * SXH + c8;
                *(uint4*)&sx[so] = *(const uint4*)&g_xh[(b0 + row) * F + f0 + c8];
                *(uint4*)&sc[so] = *(const uint4*)&g_ch[(d0 + row) * F + f0 + c8];
                *(uint4*)&sr[so] = *(const uint4*)&g_rh[(d0 + row) * F + f0 + c8];
            }
        }
        __syncthreads();

        #pragma unroll 2
        for (int f = 0; f < TF; f += 8) {
            U4H xv[4];
            #pragma unroll
            for (int j = 0; j < 4; ++j)
                xv[j].u = *(const uint4*)&sx[(ty + 16 * j) * SXH + f];

            #pragma unroll
            for (int i = 0; i < 4; ++i) {
                U4H cv, rv;
                cv.u = *(const uint4*)&sc[(tx + 16 * i) * SXH + f];
                rv.u = *(const uint4*)&sr[(tx + 16 * i) * SXH + f];
                #pragma unroll
                for (int j = 0; j < 4; ++j) {
                    // m = r - |x - c|  ==  min(x - Wmin, Wmax - x)
                    __half2 m0 = __hsub2(rv.h[0], __habs2(__hsub2(xv[j].h[0], cv.h[0])));
                    __half2 m1 = __hsub2(rv.h[1], __habs2(__hsub2(xv[j].h[1], cv.h[1])));
                    __half2 m2 = __hsub2(rv.h[2], __habs2(__hsub2(xv[j].h[2], cv.h[2])));
                    __half2 m3 = __hsub2(rv.h[3], __habs2(__hsub2(xv[j].h[3], cv.h[3])));
                    __half2 t01 = __hmin2(m0, m1);
                    __half2 t23 = __hmin2(m2, m3);
                    acc[i][j] = __hmin2(acc[i][j], __hmin2(t01, t23));
                }
            }
        }
    }

    // Epilogue: min the two f half-lanes, store fp32.
    #pragma unroll
    for (int i = 0; i < 4; ++i)
        #pragma unroll
        for (int j = 0; j < 4; ++j) {
            float lo = __low2float (acc[i][j]);
            float hi = __high2float(acc[i][j]);
            int b = b0 + ty + 16 * j;
            int d = d0 + tx + 16 * i;
            out[b * D + d] = fminf(lo, hi);
        }
}

extern "C" void kernel_launch(void* const* d_in, const int* in_sizes, int n_in,
                              void* d_out, int out_size)
{
    const float* x    = (const float*)d_in[0];
    const float* wmin = (const float*)d_in[1];
    const float* wmax = (const float*)d_in[2];
    float* out = (float*)d_out;

    prep_x<<<B * F / (256 * 8), 256>>>(x);            // 392 CTAs
    prep_w<<<D * F / (256 * 8), 256>>>(wmin, wmax);   // 196 CTAs

    dim3 grid(D / TD, B / TB);                        // (8, 16) = 128 CTAs
    dendral_kernel<<<grid, 256>>>(out);
}